// round 1
// baseline (speedup 1.0000x reference)
#include <cuda_runtime.h>
#include <cstdint>

// Problem constants (fixed by reference setup_inputs)
#define NB  8
#define LSZ 512
#define CC  6
#define NN  (NB * LSZ)       // 4096
#define KK  9
#define NK  (NN * KK)        // 36864

#define GL_PER   (2 * LSZ - 1)      // 1023 per graph (global edges)
#define SQ_PER   (2 * (LSZ - 2))    // 1020 per graph (sequential edges)
#define GL_TOT   (NB * GL_PER)      // 8184 per row
#define SQ_TOT   (NB * SQ_PER)      // 8160 per row
#define EDGE_TOT (2 * GL_TOT + 2 * SQ_TOT)   // 32688

__device__ float4 g_atoms[NN * CC];   // (x, y, z, |x|^2) per atom channel
__device__ int    g_info[NN];         // bits 0..5: pad mask per channel; bit 6: global(BOS)

// ---------------------------------------------------------------------------
// Kernel 1: precompute per-node packed atoms + pad/global masks
// ---------------------------------------------------------------------------
__global__ void prep_kernel(const float* __restrict__ X,
                            const int* __restrict__ AP,
                            const int* __restrict__ S) {
    int i = blockIdx.x * blockDim.x + threadIdx.x;
    if (i >= NN) return;
    int mask = 0;
#pragma unroll
    for (int c = 0; c < CC; c++) {
        float x = X[(i * CC + c) * 3 + 0];
        float y = X[(i * CC + c) * 3 + 1];
        float z = X[(i * CC + c) * 3 + 2];
        float sq = x * x + y * y + z * z;
        g_atoms[i * CC + c] = make_float4(x, y, z, sq);
        if (AP[i * CC + c] == 0) mask |= (1 << c);
    }
    if (S[i] == 0) mask |= 64;   // BOS / global node
    g_info[i] = mask;
}

// ---------------------------------------------------------------------------
// Kernel 2: per-row min-atom-pair distance + top-9 selection (exact tie-break)
// One CTA per row i; 128 threads; thread t handles columns t, t+128, t+256, t+384.
// ---------------------------------------------------------------------------
__global__ void __launch_bounds__(128)
knn_kernel(const int* __restrict__ sec, float* __restrict__ out) {
    const int i   = blockIdx.x;
    const int b   = i >> 9;            // graph id
    const int tid = threadIdx.x;

    __shared__ float4 sAi[CC];
    __shared__ int sInfo[2];
    __shared__ unsigned long long wOut[4 * KK];
    __shared__ unsigned long long fin[KK];

    if (tid < CC) sAi[tid] = g_atoms[i * CC + tid];
    if (tid == 0) { sInfo[0] = g_info[i]; sInfo[1] = sec[i]; }
    __syncthreads();

    const int infoI = sInfo[0];

    // Global (BOS) row: entire dist row is 1e10 -> dknn=1e10, valid=0, dst=-1.
    if (infoI & 64) {
        if (tid < KK) {
            out[0 * NK + i * KK + tid] = 1e10f;
            out[1 * NK + i * KK + tid] = (float)i;
            out[2 * NK + i * KK + tid] = -1.0f;
            out[3 * NK + i * KK + tid] = 0.0f;
        }
        return;
    }

    float4 A[CC];
#pragma unroll
    for (int c = 0; c < CC; c++) A[c] = sAi[c];
    const bool hasVI = (infoI & 63) != 63;

    unsigned long long loc[4];
#pragma unroll
    for (int t = 0; t < 4; t++) {
        const int jl = tid + t * 128;
        const int j  = (b << 9) + jl;
        const int infoJ = g_info[j];
        float dist;
        if (infoJ & 64) {
            dist = 1e10f;     // column is global node
        } else {
            float4 Bv[CC];
#pragma unroll
            for (int d = 0; d < CC; d++) Bv[d] = g_atoms[j * CC + d];
            float m2a = 3.4e38f;   // min d2 over all 36 pairs
            float m2v = 3.4e38f;   // min d2 over non-padded pairs
#pragma unroll
            for (int c = 0; c < CC; c++) {
                const bool pc = (infoI >> c) & 1;
#pragma unroll
                for (int d = 0; d < CC; d++) {
                    const bool pd = (infoJ >> d) & 1;
                    float dot = fmaf(A[c].x, Bv[d].x,
                                fmaf(A[c].y, Bv[d].y, A[c].z * Bv[d].z));
                    float r = fmaf(-2.0f, dot, A[c].w + Bv[d].w);
                    r = fmaxf(r, 0.0f);
                    m2a = fminf(m2a, r);
                    m2v = fminf(m2v, (pc || pd) ? 3.4e38f : r);
                }
            }
            const bool anyv = hasVI && ((infoJ & 63) != 63);
            // sqrt hoisted out of the 36-way min (monotone); padded-only case
            // reproduces reference's (min sqrt(d2)) + 1e10 exactly.
            dist = anyv ? sqrtf(m2v) : (1e10f + sqrtf(m2a));
        }
        // dist >= 0 always -> IEEE bits are order-preserving as uint.
        loc[t] = ((unsigned long long)__float_as_uint(dist) << 32) | (unsigned)jl;
    }

    // sort the 4 local keys ascending (network)
#define CSWAP(a_, b_) { if (loc[a_] > loc[b_]) { unsigned long long t_ = loc[a_]; loc[a_] = loc[b_]; loc[b_] = t_; } }
    CSWAP(0, 1) CSWAP(2, 3) CSWAP(0, 2) CSWAP(1, 3) CSWAP(1, 2)
#undef CSWAP

    // per-warp: 9 rounds of argmin over the warp's 128 values
    const int wid  = tid >> 5;
    const int lane = tid & 31;
    int ptr = 0;
    for (int r = 0; r < KK; r++) {
        unsigned long long key = (ptr < 4) ? loc[ptr] : 0xFFFFFFFFFFFFFFFFULL;
        unsigned long long m = key;
#pragma unroll
        for (int o = 16; o > 0; o >>= 1) {
            unsigned long long other = __shfl_xor_sync(0xFFFFFFFFu, m, o);
            m = min(m, other);
        }
        if (key == m) ptr++;        // unique keys (index in low bits) -> one winner
        if (lane == 0) wOut[wid * KK + r] = m;
    }
    __syncthreads();

    // merge 4 sorted 9-lists -> first 9 (serial, ~36 compares)
    if (tid == 0) {
        int p[4] = {0, 0, 0, 0};
        for (int r = 0; r < KK; r++) {
            unsigned long long best = 0xFFFFFFFFFFFFFFFFULL;
            int bw = 0;
#pragma unroll
            for (int w = 0; w < 4; w++) {
                if (p[w] < KK) {
                    unsigned long long v = wOut[w * KK + p[w]];
                    if (v < best) { best = v; bw = w; }
                }
            }
            p[bw]++;
            fin[r] = best;
        }
    }
    __syncthreads();

    if (tid < KK) {
        unsigned long long v = fin[tid];
        float d  = __uint_as_float((unsigned)(v >> 32));
        int   jl = (int)(v & 0xFFFFFFFFu);
        int  dst = (b << 9) + jl;
        bool valid = (d < 1e10f) && (sInfo[1] == sec[dst]);
        out[0 * NK + i * KK + tid] = d;
        out[1 * NK + i * KK + tid] = (float)i;
        out[2 * NK + i * KK + tid] = valid ? (float)dst : -1.0f;
        out[3 * NK + i * KK + tid] = valid ? 1.0f : 0.0f;
    }
}

// ---------------------------------------------------------------------------
// Kernel 3: static global + sequential edge lists (computed, not loaded)
// ---------------------------------------------------------------------------
__global__ void edges_kernel(float* __restrict__ out) {
    int t = blockIdx.x * blockDim.x + threadIdx.x;
    if (t >= EDGE_TOT) return;
    int val;
    if (t < 2 * GL_TOT) {
        int r = t / GL_TOT, u = t % GL_TOT;
        int b = u / GL_PER, q = u % GL_PER;
        if (r == 0) val = (q < LSZ) ? 0 : (q - (LSZ - 1));   // src: zeros(L), 1..L-1
        else        val = (q < LSZ) ? q : 0;                 // dst: 0..L-1, zeros(L-1)
        val += b * LSZ;
    } else {
        int t2 = t - 2 * GL_TOT;
        int r = t2 / SQ_TOT, u = t2 % SQ_TOT;
        int b = u / SQ_PER, q = u % SQ_PER;
        if (r == 0) val = (q < LSZ - 2) ? (q + 1) : (q - (LSZ - 2) + 2);  // a, a+1
        else        val = (q < LSZ - 2) ? (q + 2) : (q - (LSZ - 2) + 1);  // a+1, a
        val += b * LSZ;
    }
    out[4 * NK + t] = (float)val;
}

// ---------------------------------------------------------------------------
extern "C" void kernel_launch(void* const* d_in, const int* in_sizes, int n_in,
                              void* d_out, int out_size) {
    const float* X   = (const float*)d_in[0];
    const int*   AP  = (const int*)d_in[1];
    const int*   S   = (const int*)d_in[2];
    const int*   sec = (const int*)d_in[3];
    // d_in[4] = batch_id (implied by layout), d_in[5] = k (=9, compile-time)
    float* out = (float*)d_out;

    prep_kernel<<<(NN + 127) / 128, 128>>>(X, AP, S);
    knn_kernel<<<NN, 128>>>(sec, out);
    edges_kernel<<<(EDGE_TOT + 255) / 256, 256>>>(out);
}